// round 6
// baseline (speedup 1.0000x reference)
#include <cuda_runtime.h>
#include <math.h>

#define T_STEPS 1024
#define HID     256
#define G4      1024          // 4*HID
#define NSPK    1251
#define CPL     32            // CTAs per layer
#define UPC     8             // units per CTA (= warps per CTA)
#define KSL     32            // k-slice per thread (256/8)

// -------- device scratch (no allocations allowed) --------
__device__ float g_h[3][T_STEPS + 1][HID];     // h history per layer (NaN = not yet written)
__device__ float g_xg0[T_STEPS][G4];           // layer-0 input projections (+biases)
__device__ float g_logits[T_STEPS][NSPK];      // pre-softmax logits

#define SENT_BITS 0x7FC00001u

// ============================================================
// Reset kernel: t=0 rows -> 0.0f, t>=1 rows -> NaN sentinel.
// ============================================================
__global__ void reset_kernel() {
    int idx = blockIdx.x * blockDim.x + threadIdx.x;
    const int per = (T_STEPS + 1) * HID;
    const int total = 3 * per;
    if (idx < total) {
        int rem = idx % per;
        int t = rem / HID;
        ((unsigned*)g_h)[idx] = (t == 0) ? 0u : SENT_BITS;
    }
}

// ============================================================
// Layer-0 input projection: xg0[t][g] = b_ih0[g]+b_hh0[g] + x[63,t,:]·w_ih0[g,:]
// ============================================================
__global__ void xg0_kernel(const float* __restrict__ x,
                           const float* __restrict__ w_ih0,
                           const float* __restrict__ b_ih0,
                           const float* __restrict__ b_hh0) {
    int t   = blockIdx.x;
    int tid = threadIdx.x;
    __shared__ float xr[40];
    if (tid < 40) xr[tid] = x[(63 * T_STEPS + t) * 40 + tid];
    __syncthreads();
#pragma unroll
    for (int q = 0; q < 4; q++) {
        int g = q * 256 + tid;
        float acc = b_ih0[g] + b_hh0[g];
        const float* w = w_ih0 + g * 40;
#pragma unroll
        for (int f = 0; f < 40; f++) acc = fmaf(w[f], xr[f], acc);
        g_xg0[t][g] = acc;
    }
}

// ============================================================
// helpers
// ============================================================
__device__ __forceinline__ float4 ldcg4(const float* p) {
    float4 v;
    asm volatile("ld.global.cg.v4.f32 {%0,%1,%2,%3},[%4];"
                 : "=f"(v.x), "=f"(v.y), "=f"(v.z), "=f"(v.w) : "l"(p));
    return v;
}
__device__ __forceinline__ bool ok4(float4 v) {
    return (v.x == v.x) & (v.y == v.y) & (v.z == v.z) & (v.w == v.w);
}

// ============================================================
// Persistent wavefront LSTM kernel. 96 CTAs (3 layers x 32), 256 thr.
// Warp w = unit base_u+w. lane = q*8+kp: gate q (i,f,g,o), k-slice kp.
// Whole step loop is barrier-free and smem-free: each thread polls its own
// 32-float slice of the needed h vectors straight from L2 into registers
// (NaN-sentinel scheme: the value IS the ready flag), FMAs against
// register-resident weights, reduces with 3 shfl_xor, activates gates in
// parallel across lanes, and lane 0 publishes h with one STG.
// ============================================================
__global__ void __launch_bounds__(256, 1)
lstm_kernel(const float* __restrict__ w_hh0,
            const float* __restrict__ w_ih1, const float* __restrict__ w_hh1,
            const float* __restrict__ b_ih1, const float* __restrict__ b_hh1,
            const float* __restrict__ w_ih2, const float* __restrict__ w_hh2,
            const float* __restrict__ b_ih2, const float* __restrict__ b_hh2) {
    const int l      = blockIdx.x >> 5;
    const int cidx   = blockIdx.x & 31;
    const int base_u = cidx * UPC;
    const int tid    = threadIdx.x;
    const int w      = tid >> 5;        // warp = unit index
    const int lane   = tid & 31;
    const int q      = lane >> 3;       // gate: 0=i,1=f,2=g,3=o
    const int kp     = lane & 7;        // k-slice
    const int u      = base_u + w;
    const int grow   = q * 256 + u;     // global gate row

    const float* Whh = (l == 0) ? w_hh0 : (l == 1) ? w_hh1 : w_hh2;
    const float* Wih = (l == 1) ? w_ih1 : w_ih2;
    const float* Bih = (l == 1) ? b_ih1 : b_ih2;
    const float* Bhh = (l == 1) ? b_hh1 : b_hh2;

    // ---- register-resident weight slices ----
    float whh[KSL], wih[KSL];
    {
        const float* wr = Whh + grow * HID + kp * KSL;
#pragma unroll
        for (int j = 0; j < KSL / 4; j++) {
            float4 v = *(const float4*)(wr + 4 * j);
            whh[4 * j + 0] = v.x; whh[4 * j + 1] = v.y;
            whh[4 * j + 2] = v.z; whh[4 * j + 3] = v.w;
        }
    }
    if (l > 0) {
        const float* wr = Wih + grow * HID + kp * KSL;
#pragma unroll
        for (int j = 0; j < KSL / 4; j++) {
            float4 v = *(const float4*)(wr + 4 * j);
            wih[4 * j + 0] = v.x; wih[4 * j + 1] = v.y;
            wih[4 * j + 2] = v.z; wih[4 * j + 3] = v.w;
        }
    }

    float xb = 0.f;
    if (l > 0) xb = Bih[grow] + Bhh[grow];   // bias (same across kp; used post-reduce)

    const float* pA = &g_h[l][0][kp * KSL];                      // own layer, t-1
    const float* pB = (l > 0) ? &g_h[l - 1][1][kp * KSL] : 0;    // lower layer, t
    float*       po = &g_h[l][1][u];                             // publish target

    float c_state = 0.f;

    for (int t = 1; t <= T_STEPS; t++) {
        // addend for this row: layer-0 reads precomputed xg (issued before the
        // poll so it's in flight); layers 1,2 use the constant bias sum.
        float addend = xb;
        if (l == 0) addend = __ldg(&g_xg0[t - 1][grow]);

        float4 vA[8], vB[8];
        // ---- joint sentinel poll: exit when ALL needed inputs are clean ----
        if (l == 0) {
            int spins = 0;
            for (;;) {
#pragma unroll
                for (int j = 0; j < 8; j++) vA[j] = ldcg4(pA + 4 * j);
                bool ok = true;
#pragma unroll
                for (int j = 0; j < 8; j++) ok &= ok4(vA[j]);
                if (ok) break;
                if (++spins > 2048) __nanosleep(64);
            }
        } else {
            int spins = 0;
            for (;;) {
#pragma unroll
                for (int j = 0; j < 8; j++) vA[j] = ldcg4(pA + 4 * j);
#pragma unroll
                for (int j = 0; j < 8; j++) vB[j] = ldcg4(pB + 4 * j);
                bool ok = true;
#pragma unroll
                for (int j = 0; j < 8; j++) ok &= ok4(vA[j]);
#pragma unroll
                for (int j = 0; j < 8; j++) ok &= ok4(vB[j]);
                if (ok) break;
                if (++spins > 2048) __nanosleep(64);
            }
        }

        // ---- matvec slice: 4 accumulators ----
        float a0 = 0.f, a1 = 0.f, a2 = 0.f, a3 = 0.f;
#pragma unroll
        for (int j = 0; j < 8; j++) {
            a0 = fmaf(whh[4 * j + 0], vA[j].x, a0);
            a1 = fmaf(whh[4 * j + 1], vA[j].y, a1);
            a2 = fmaf(whh[4 * j + 2], vA[j].z, a2);
            a3 = fmaf(whh[4 * j + 3], vA[j].w, a3);
        }
        if (l > 0) {
#pragma unroll
            for (int j = 0; j < 8; j++) {
                a0 = fmaf(wih[4 * j + 0], vB[j].x, a0);
                a1 = fmaf(wih[4 * j + 1], vB[j].y, a1);
                a2 = fmaf(wih[4 * j + 2], vB[j].z, a2);
                a3 = fmaf(wih[4 * j + 3], vB[j].w, a3);
            }
        }
        float acc = (a0 + a1) + (a2 + a3);
        // 8-way reduce across kp (lane bits 0..2); all lanes get group sum
        acc += __shfl_xor_sync(0xffffffffu, acc, 1);
        acc += __shfl_xor_sync(0xffffffffu, acc, 2);
        acc += __shfl_xor_sync(0xffffffffu, acc, 4);

        // ---- gate activation, parallel across lanes (branchless) ----
        float g = acc + addend;
        // q==2 -> tanh(g) = 2*sigma(2g)-1 ; else sigmoid(g). Same MUFU path.
        float sc = (q == 2) ? 2.f : 1.f;
        float e  = __expf(-sc * g);
        float rr = __fdividef(1.f, 1.f + e);
        float act = (q == 2) ? fmaf(2.f, rr, -1.f) : rr;

        // gather the 4 gates of this warp's unit (from lanes 0,8,16,24)
        float gi = __shfl_sync(0xffffffffu, act, 0);
        float gf = __shfl_sync(0xffffffffu, act, 8);
        float gg = __shfl_sync(0xffffffffu, act, 16);
        float go = __shfl_sync(0xffffffffu, act, 24);

        c_state = fmaf(gf, c_state, gi * gg);
        float ec = __expf(-2.f * c_state);
        float tc = fmaf(2.f, __fdividef(1.f, 1.f + ec), -1.f);
        float h  = go * tc;
        if (lane == 0) __stcg(po, h);   // value IS the ready flag

        pA += HID;
        if (l > 0) pB += HID;
        po += HID;
    }
}

// ============================================================
// Final linear: logits[t][n] = b_lin[n] + h2[t]·w_lin[n]
// 64x64 tiles, k-chunks of 32, 256 threads, acc 4x4 per thread.
// ============================================================
__global__ void lin_kernel(const float* __restrict__ w_lin,
                           const float* __restrict__ b_lin) {
    const int n0  = blockIdx.x * 64;
    const int t0  = blockIdx.y * 64;
    const int tid = threadIdx.x;
    const int ti  = tid & 15;   // t sub-index
    const int nj  = tid >> 4;   // n sub-index

    __shared__ float As[64][36];
    __shared__ float Bs[64][36];

    float acc[4][4];
#pragma unroll
    for (int m = 0; m < 4; m++)
#pragma unroll
        for (int n = 0; n < 4; n++) acc[m][n] = 0.f;

    const int lrow = tid >> 2;
    const int lc0  = (tid & 3) * 8;

    for (int kc = 0; kc < HID; kc += 32) {
        {
            const float* src = &g_h[2][t0 + lrow + 1][kc + lc0];
            float4 v0 = *(const float4*)src;
            float4 v1 = *(const float4*)(src + 4);
            *(float4*)&As[lrow][lc0]     = v0;
            *(float4*)&As[lrow][lc0 + 4] = v1;
        }
        {
            int n = n0 + lrow;
            float4 v0 = make_float4(0.f, 0.f, 0.f, 0.f);
            float4 v1 = make_float4(0.f, 0.f, 0.f, 0.f);
            if (n < NSPK) {
                const float* src = &w_lin[n * HID + kc + lc0];
                v0 = *(const float4*)src;
                v1 = *(const float4*)(src + 4);
            }
            *(float4*)&Bs[lrow][lc0]     = v0;
            *(float4*)&Bs[lrow][lc0 + 4] = v1;
        }
        __syncthreads();
#pragma unroll
        for (int kk = 0; kk < 32; kk++) {
            float a[4], b[4];
#pragma unroll
            for (int m = 0; m < 4; m++) a[m] = As[ti + 16 * m][kk];
#pragma unroll
            for (int n = 0; n < 4; n++) b[n] = Bs[nj + 16 * n][kk];
#pragma unroll
            for (int m = 0; m < 4; m++)
#pragma unroll
                for (int n = 0; n < 4; n++)
                    acc[m][n] = fmaf(a[m], b[n], acc[m][n]);
        }
        __syncthreads();
    }
#pragma unroll
    for (int m = 0; m < 4; m++) {
        int t = t0 + ti + 16 * m;
#pragma unroll
        for (int n = 0; n < 4; n++) {
            int nn = n0 + nj + 16 * n;
            if (nn < NSPK) g_logits[t][nn] = acc[m][n] + b_lin[nn];
        }
    }
}

// ============================================================
// Row-wise log_softmax over NSPK, one block per t.
// ============================================================
__global__ void lsm_kernel(float* __restrict__ out) {
    const int t   = blockIdx.x;
    const int tid = threadIdx.x;
    const int lane = tid & 31;
    const int wid  = tid >> 5;

    float v[5];
    float mx = -INFINITY;
#pragma unroll
    for (int m = 0; m < 5; m++) {
        int n = tid + m * 256;
        v[m] = (n < NSPK) ? g_logits[t][n] : -INFINITY;
        mx = fmaxf(mx, v[m]);
    }
    __shared__ float smax[8];
    __shared__ float ssum[8];
#pragma unroll
    for (int o = 16; o > 0; o >>= 1) mx = fmaxf(mx, __shfl_xor_sync(0xffffffffu, mx, o));
    if (lane == 0) smax[wid] = mx;
    __syncthreads();
    mx = smax[0];
#pragma unroll
    for (int w = 1; w < 8; w++) mx = fmaxf(mx, smax[w]);

    float s = 0.f;
#pragma unroll
    for (int m = 0; m < 5; m++) {
        int n = tid + m * 256;
        if (n < NSPK) s += __expf(v[m] - mx);
    }
#pragma unroll
    for (int o = 16; o > 0; o >>= 1) s += __shfl_xor_sync(0xffffffffu, s, o);
    if (lane == 0) ssum[wid] = s;
    __syncthreads();
    s = ssum[0];
#pragma unroll
    for (int w = 1; w < 8; w++) s += ssum[w];

    float lg = logf(s) + mx;
#pragma unroll
    for (int m = 0; m < 5; m++) {
        int n = tid + m * 256;
        if (n < NSPK) out[t * NSPK + n] = v[m] - lg;
    }
}

// ============================================================
extern "C" void kernel_launch(void* const* d_in, const int* in_sizes, int n_in,
                              void* d_out, int out_size) {
    const float* x     = (const float*)d_in[0];
    const float* w_ih0 = (const float*)d_in[1];
    const float* w_hh0 = (const float*)d_in[2];
    const float* b_ih0 = (const float*)d_in[3];
    const float* b_hh0 = (const float*)d_in[4];
    const float* w_ih1 = (const float*)d_in[5];
    const float* w_hh1 = (const float*)d_in[6];
    const float* b_ih1 = (const float*)d_in[7];
    const float* b_hh1 = (const float*)d_in[8];
    const float* w_ih2 = (const float*)d_in[9];
    const float* w_hh2 = (const float*)d_in[10];
    const float* b_ih2 = (const float*)d_in[11];
    const float* b_hh2 = (const float*)d_in[12];
    const float* w_lin = (const float*)d_in[13];
    const float* b_lin = (const float*)d_in[14];

    const int reset_total = 3 * (T_STEPS + 1) * HID;
    reset_kernel<<<(reset_total + 1023) / 1024, 1024>>>();
    xg0_kernel<<<T_STEPS, 256>>>(x, w_ih0, b_ih0, b_hh0);
    lstm_kernel<<<3 * CPL, 256>>>(w_hh0, w_ih1, w_hh1, b_ih1, b_hh1,
                                  w_ih2, w_hh2, b_ih2, b_hh2);
    dim3 gl((NSPK + 63) / 64, T_STEPS / 64);
    lin_kernel<<<gl, 256>>>(w_lin, b_lin);
    lsm_kernel<<<T_STEPS, 256>>>((float*)d_out);
}